// round 1
// baseline (speedup 1.0000x reference)
#include <cuda_runtime.h>

#define NN 32
#define CC 64
#define OO 64
#define TT 512
#define VV 25
#define SS 3
#define RR 32
#define EPSV 1e-5f
#define TB 8            // t-tile per block
#define NTB (TT/TB)     // 64 t-blocks

// ---- scratch (static __device__; no allocations allowed) ----
__device__ float g_xm[NN*CC*VV];                 // mean over T
__device__ float g_att[NN*SS*OO*VV*VV];          // attention tensor
__device__ float g_ybias[NN*OO*VV];              // sum_s b3 * rowsum(att)
__device__ float g_y[NN*OO*TT*VV];               // pre-BN output
__device__ float g_sum[OO];
__device__ float g_sumsq[OO];
__device__ float g_scale[OO];
__device__ float g_shift[OO];

// ---------------------------------------------------------------------------
// Kernel 1: xm[n,c,v] = mean_t x[n,c,t,v]
// ---------------------------------------------------------------------------
__global__ void k_xm(const float* __restrict__ x) {
    int idx = blockIdx.x * blockDim.x + threadIdx.x;   // (n*CC+c)*VV+v
    if (idx >= NN*CC*VV) return;
    int v  = idx % VV;
    int nc = idx / VV;
    const float* p = x + (size_t)nc * (TT*VV) + v;
    float a0=0.f, a1=0.f, a2=0.f, a3=0.f;
    #pragma unroll 4
    for (int t = 0; t < TT; t += 4) {
        a0 += p[(t+0)*VV]; a1 += p[(t+1)*VV];
        a2 += p[(t+2)*VV]; a3 += p[(t+3)*VV];
    }
    g_xm[idx] = (a0+a1+a2+a3) * (1.0f/(float)TT);
}

// ---------------------------------------------------------------------------
// Kernel 2: att[n,s,o,u,v] = alpha[s]*(sum_r w4[s,o,r]*relu(q[r,u]-k[r,v]) + b4[s,o]) + A[s,u,v]
// block = (n,s), 256 threads
// ---------------------------------------------------------------------------
__global__ void k_att(const float* __restrict__ w1, const float* __restrict__ b1,
                      const float* __restrict__ w2, const float* __restrict__ b2,
                      const float* __restrict__ w4, const float* __restrict__ b4,
                      const float* __restrict__ alpha, const float* __restrict__ A) {
    int n = blockIdx.x / SS, s = blockIdx.x % SS;
    __shared__ float xm_sm[CC*VV];
    __shared__ float q_sm[RR*VV];
    __shared__ float k_sm[RR*VV];
    __shared__ float w4_sm[OO*RR];
    __shared__ float b4_sm[OO];
    int tid = threadIdx.x;

    for (int i = tid; i < CC*VV; i += blockDim.x) xm_sm[i] = g_xm[n*CC*VV + i];
    for (int i = tid; i < OO*RR; i += blockDim.x) w4_sm[i] = w4[s*OO*RR + i];
    if (tid < OO) b4_sm[tid] = b4[s*OO + tid];
    __syncthreads();

    for (int e = tid; e < RR*VV; e += blockDim.x) {
        int r = e / VV, v = e % VV;
        const float* w1r = w1 + (s*RR + r)*CC;
        const float* w2r = w2 + (s*RR + r)*CC;
        float accq = b1[s*RR + r], acck = b2[s*RR + r];
        #pragma unroll 8
        for (int c = 0; c < CC; c++) {
            float xv = xm_sm[c*VV + v];
            accq = fmaf(w1r[c], xv, accq);
            acck = fmaf(w2r[c], xv, acck);
        }
        q_sm[e] = accq; k_sm[e] = acck;
    }
    __syncthreads();

    float al = alpha[s];
    for (int uv = tid; uv < VV*VV; uv += blockDim.x) {
        int u = uv / VV, v = uv % VV;
        float rel[RR];
        #pragma unroll
        for (int r = 0; r < RR; r++)
            rel[r] = fmaxf(q_sm[r*VV + u] - k_sm[r*VV + v], 0.f);
        float Auv = A[(s*VV + u)*VV + v];
        float* outp = g_att + (size_t)((n*SS + s)*OO) * (VV*VV) + uv;
        for (int o = 0; o < OO; o++) {
            float acc = 0.f;
            #pragma unroll
            for (int r = 0; r < RR; r++)
                acc = fmaf(w4_sm[o*RR + r], rel[r], acc);
            outp[o*VV*VV] = al*(acc + b4_sm[o]) + Auv;
        }
    }
}

// ---------------------------------------------------------------------------
// Kernel 3: ybias[n,o,u] = sum_s b3[s,o] * sum_v att[n,s,o,u,v]; also zero stats
// ---------------------------------------------------------------------------
__global__ void k_ybias(const float* __restrict__ b3) {
    int n = blockIdx.x;
    int tid = threadIdx.x;
    if (n == 0) {
        if (tid < OO)                 g_sum[tid] = 0.f;
        else if (tid < 2*OO)          g_sumsq[tid - OO] = 0.f;
    }
    for (int e = tid; e < OO*VV; e += blockDim.x) {
        int o = e / VV, u = e % VV;
        float acc = 0.f;
        #pragma unroll
        for (int s = 0; s < SS; s++) {
            const float* ap = g_att + (size_t)(((n*SS + s)*OO + o)*VV + u) * VV;
            float rs = 0.f;
            #pragma unroll
            for (int v = 0; v < VV; v++) rs += ap[v];
            acc = fmaf(b3[s*OO + o], rs, acc);
        }
        g_ybias[n*OO*VV + e] = acc;
    }
}

// ---------------------------------------------------------------------------
// Kernel 4 (main): fused v = w3@x  and  y += att @ v, per (n, t-tile) block.
// 512 threads = 16 warps; warp w owns o in [4w, 4w+4).
// smem: xs[64][200] | vs[16][200] | ws[16][64*4] | atts[16][800]
// ---------------------------------------------------------------------------
#define SMEM_FLOATS (12800 + 3200 + 4096 + 12800)   // 32,896 floats = 131,584 B
__global__ void __launch_bounds__(512, 1)
k_main(const float* __restrict__ x, const float* __restrict__ w3) {
    extern __shared__ float sm[];
    float* xs   = sm;              // [c][tv]   12800
    float* vs   = sm + 12800;      // [w][tv]    3200
    float* ws   = sm + 16000;      // [w][c*4+oq] 4096 (float4-aligned)
    float* atts = sm + 20096;      // [w][800]  12800

    int n  = blockIdx.x / NTB;
    int tb = blockIdx.x % NTB;
    int t0 = tb * TB;
    int tid = threadIdx.x, w = tid >> 5, lane = tid & 31;

    // --- load x tile: [C][TB*VV] (200 contiguous floats per c-row) ---
    float4* xs4 = (float4*)xs;
    for (int i = tid; i < CC*50; i += 512) {
        int c = i / 50, q = i % 50;
        xs4[c*50 + q] = *(const float4*)(x + (size_t)(n*CC + c)*(TT*VV) + t0*VV + q*4);
    }
    __syncthreads();

    int o0 = w * 4;
    int tp = lane >> 3;    // t pair: t in {2tp, 2tp+1}
    int ug = lane & 7;     // u group: u in {4ug..4ug+3} (guarded, u<25)

    // y accumulators, initialized with ybias (same for both t's)
    float acc2[4][2][4];
    #pragma unroll
    for (int oq = 0; oq < 4; oq++)
        #pragma unroll
        for (int i = 0; i < 4; i++) {
            int u = 4*ug + i;
            float yb = (u < VV) ? g_ybias[(n*OO + o0 + oq)*VV + u] : 0.f;
            acc2[oq][0][i] = yb; acc2[oq][1][i] = yb;
        }

    float* vsw  = vs  + w*200;
    float* wsw  = ws  + w*256;
    float* attw = atts + w*800;

    for (int s = 0; s < SS; s++) {
        // w3 quad for this warp's 4 o's, layout [c][oq] for float4 broadcast
        __syncwarp();
        for (int i = lane; i < 256; i += 32) {
            int c = i >> 2, oq = i & 3;
            wsw[i] = w3[(size_t)(s*OO + o0 + oq)*CC + c];
        }
        __syncwarp();

        // ---- v-stage: acc[oq][j] = sum_c w3[o,c] * x[c, lane+32j] ----
        float acc[4][7];
        #pragma unroll
        for (int oq = 0; oq < 4; oq++)
            #pragma unroll
            for (int j = 0; j < 7; j++) acc[oq][j] = 0.f;

        const float4* wsw4 = (const float4*)wsw;
        #pragma unroll 2
        for (int c = 0; c < CC; c++) {
            float4 wv = wsw4[c];
            const float* xr = xs + c*200 + lane;
            float xv[7];
            #pragma unroll
            for (int j = 0; j < 6; j++) xv[j] = xr[32*j];
            xv[6] = (lane < 8) ? xr[192] : 0.f;
            #pragma unroll
            for (int j = 0; j < 7; j++) {
                acc[0][j] = fmaf(wv.x, xv[j], acc[0][j]);
                acc[1][j] = fmaf(wv.y, xv[j], acc[1][j]);
                acc[2][j] = fmaf(wv.z, xv[j], acc[2][j]);
                acc[3][j] = fmaf(wv.w, xv[j], acc[3][j]);
            }
        }

        // ---- y-stage per o in quad ----
        for (int oq = 0; oq < 4; oq++) {
            __syncwarp();
            // dump v tile to smem
            #pragma unroll
            for (int j = 0; j < 6; j++) vsw[lane + 32*j] = acc[oq][j];
            if (lane < 8) vsw[lane + 192] = acc[oq][6];
            // stage att row (625 floats; pad region [625,800) read-but-discarded)
            const float* ag = g_att + (size_t)((n*SS + s)*OO + o0 + oq) * (VV*VV);
            for (int i = lane; i < VV*VV; i += 32) attw[i] = ag[i];
            __syncwarp();

            const float* va = vsw + (2*tp)*VV;
            const float* vb = va + VV;
            const float* au = attw + (4*ug)*VV;
            #pragma unroll
            for (int v = 0; v < VV; v++) {
                float fa = va[v], fb = vb[v];
                float a0 = au[v], a1 = au[VV + v], a2 = au[2*VV + v], a3 = au[3*VV + v];
                acc2[oq][0][0] = fmaf(a0, fa, acc2[oq][0][0]);
                acc2[oq][1][0] = fmaf(a0, fb, acc2[oq][1][0]);
                acc2[oq][0][1] = fmaf(a1, fa, acc2[oq][0][1]);
                acc2[oq][1][1] = fmaf(a1, fb, acc2[oq][1][1]);
                acc2[oq][0][2] = fmaf(a2, fa, acc2[oq][0][2]);
                acc2[oq][1][2] = fmaf(a2, fb, acc2[oq][1][2]);
                acc2[oq][0][3] = fmaf(a3, fa, acc2[oq][0][3]);
                acc2[oq][1][3] = fmaf(a3, fb, acc2[oq][1][3]);
            }
        }
    }

    // ---- epilogue: write y, accumulate BN stats ----
    #pragma unroll
    for (int oq = 0; oq < 4; oq++) {
        int o = o0 + oq;
        float ps = 0.f, pss = 0.f;
        #pragma unroll
        for (int j = 0; j < 2; j++) {
            int t = 2*tp + j;
            #pragma unroll
            for (int i = 0; i < 4; i++) {
                int u = 4*ug + i;
                if (u < VV) {
                    float val = acc2[oq][j][i];
                    g_y[((size_t)(n*OO + o)*TT + t0 + t)*VV + u] = val;
                    ps  += val;
                    pss += val*val;
                }
            }
        }
        #pragma unroll
        for (int off = 16; off > 0; off >>= 1) {
            ps  += __shfl_xor_sync(0xffffffffu, ps,  off);
            pss += __shfl_xor_sync(0xffffffffu, pss, off);
        }
        if (lane == 0) {
            atomicAdd(&g_sum[o],   ps);
            atomicAdd(&g_sumsq[o], pss);
        }
    }
}

// ---------------------------------------------------------------------------
// Kernel 5: BN scale/shift from accumulated stats
// ---------------------------------------------------------------------------
__global__ void k_bnp(const float* __restrict__ gamma, const float* __restrict__ beta) {
    int o = threadIdx.x;
    if (o < OO) {
        float cnt = (float)(NN*TT*VV);
        float mu  = g_sum[o] / cnt;
        float var = g_sumsq[o] / cnt - mu*mu;
        float sc  = gamma[o] * rsqrtf(var + EPSV);
        g_scale[o] = sc;
        g_shift[o] = beta[o] - mu*sc;
    }
}

// ---------------------------------------------------------------------------
// Kernel 6: out = relu(y) + y*scale + shift + x
// ---------------------------------------------------------------------------
__global__ void k_final(const float* __restrict__ x, float* __restrict__ out) {
    const int total4 = NN*OO*TT*VV / 4;
    for (int i = blockIdx.x*blockDim.x + threadIdx.x; i < total4; i += gridDim.x*blockDim.x) {
        int c = (i / (TT*VV/4)) % OO;
        float sc = g_scale[c], sh = g_shift[c];
        float4 y4 = ((const float4*)g_y)[i];
        float4 x4 = ((const float4*)x)[i];
        float4 r;
        r.x = fmaxf(y4.x, 0.f) + fmaf(y4.x, sc, sh) + x4.x;
        r.y = fmaxf(y4.y, 0.f) + fmaf(y4.y, sc, sh) + x4.y;
        r.z = fmaxf(y4.z, 0.f) + fmaf(y4.z, sc, sh) + x4.z;
        r.w = fmaxf(y4.w, 0.f) + fmaf(y4.w, sc, sh) + x4.w;
        ((float4*)out)[i] = r;
    }
}

// ---------------------------------------------------------------------------
extern "C" void kernel_launch(void* const* d_in, const int* in_sizes, int n_in,
                              void* d_out, int out_size) {
    (void)in_sizes; (void)n_in; (void)out_size;
    const float* x     = (const float*)d_in[0];
    const float* A     = (const float*)d_in[1];
    const float* w1    = (const float*)d_in[2];
    const float* b1    = (const float*)d_in[3];
    const float* w2    = (const float*)d_in[4];
    const float* b2    = (const float*)d_in[5];
    const float* w3    = (const float*)d_in[6];
    const float* b3    = (const float*)d_in[7];
    const float* w4    = (const float*)d_in[8];
    const float* b4    = (const float*)d_in[9];
    const float* alpha = (const float*)d_in[10];
    const float* gamma = (const float*)d_in[11];
    const float* beta  = (const float*)d_in[12];
    float* out = (float*)d_out;

    static const int smem_bytes = SMEM_FLOATS * (int)sizeof(float);
    cudaFuncSetAttribute(k_main, cudaFuncAttributeMaxDynamicSharedMemorySize, smem_bytes);

    k_xm   <<< (NN*CC*VV + 255)/256, 256 >>>(x);
    k_att  <<< NN*SS, 256 >>>(w1, b1, w2, b2, w4, b4, alpha, A);
    k_ybias<<< NN, 256 >>>(b3);
    k_main <<< NN*NTB, 512, smem_bytes >>>(x, w3);
    k_bnp  <<< 1, 64 >>>(gamma, beta);
    k_final<<< 2048, 256 >>>(x, out);
}